// round 17
// baseline (speedup 1.0000x reference)
#include <cuda_runtime.h>
#include <math.h>

#define NB   128
#define NG   360
#define NGI  174
#define NEF  512
#define NET  512
#define NU   512
#define NAU  32
#define NVOC 5000
#define NT   20
#define NKS  1024               // gates K: [ctx | a]
#define N4U  (4 * NU)           // 2048
#define NSK  16                 // split-K factor for gates
#define NKSP (NKS / NSK)        // 64
#define NRB  256                // persistent recurrence grid (<= 148*2 co-resident)

// ---------------- scratch (device globals; no allocation allowed) ----------------
__device__ float g_feat[(size_t)NB * NG * NEF];
__device__ float g_f1[(size_t)NB * NG * NAU];
__device__ float g_aseq[(size_t)(NT + 1) * NB * NU];
__device__ float g_c[NB * NU];
__device__ float g_xfull[NB * NKS];
__device__ float g_gpart[(size_t)NSK * NB * N4U];
__device__ float g_Wcat[(size_t)N4U * NKS];
__device__ float g_bsum[N4U];
__device__ float g_embseq[(size_t)NT * NB * NET];
__device__ float g_embg[(size_t)NT * NB * N4U];
__device__ float g_wbuf[NB * NG];
__device__ float g_d1big[(size_t)NT * NB * 256];
__device__ float g_lgbig[(size_t)NT * NB * NVOC];
__device__ unsigned int g_barCnt;

// ---------------- helpers ----------------
__device__ __forceinline__ float warpSum(float v) {
    #pragma unroll
    for (int o = 16; o; o >>= 1) v += __shfl_xor_sync(0xffffffffu, v, o);
    return v;
}
__device__ __forceinline__ float warpMax(float v) {
    #pragma unroll
    for (int o = 16; o; o >>= 1) v = fmaxf(v, __shfl_xor_sync(0xffffffffu, v, o));
    return v;
}
__device__ __forceinline__ float blockSum(float v, float* sm) {
    __syncthreads();
    int lane = threadIdx.x & 31, wid = threadIdx.x >> 5;
    v = warpSum(v);
    if (lane == 0) sm[wid] = v;
    __syncthreads();
    int nw = blockDim.x >> 5;
    float r = (threadIdx.x < nw) ? sm[threadIdx.x] : 0.f;
    if (wid == 0) { r = warpSum(r); if (lane == 0) sm[0] = r; }
    __syncthreads();
    return sm[0];
}
__device__ __forceinline__ float blockMax(float v, float* sm) {
    __syncthreads();
    int lane = threadIdx.x & 31, wid = threadIdx.x >> 5;
    v = warpMax(v);
    if (lane == 0) sm[wid] = v;
    __syncthreads();
    int nw = blockDim.x >> 5;
    float r = (threadIdx.x < nw) ? sm[threadIdx.x] : -INFINITY;
    if (wid == 0) { r = warpMax(r); if (lane == 0) sm[0] = r; }
    __syncthreads();
    return sm[0];
}
__device__ __forceinline__ float sigmoidf(float x) { return 1.f / (1.f + expf(-x)); }
__device__ __forceinline__ float leakyf(float x)  { return x >= 0.f ? x : 0.2f * x; }

// software grid barrier (monotonic counter; reset per launch in init_kernel)
__device__ __forceinline__ void grid_sync(unsigned int& epoch) {
    epoch++;
    __syncthreads();
    if (threadIdx.x == 0) {
        __threadfence();
        atomicAdd(&g_barCnt, 1u);
        unsigned int target = epoch * NRB;
        while (*(volatile unsigned int*)&g_barCnt < target) __nanosleep(64);
        __threadfence();
    }
    __syncthreads();
}

// =================== 128x128-tile SGEMM, 8x8 microtile, K-chunk 8 (scalar, proven) ====
template<bool BT, int EPI, bool EXACT>
__global__ void __launch_bounds__(256, 2) gemm128_kernel(
    const float* __restrict__ A, int lda, size_t aBatch,
    const float* __restrict__ Bm, int ldb, size_t bBatch,
    const float* __restrict__ bias, size_t biasBatch,
    float* __restrict__ C, int ldc, size_t cBatch,
    int M, int N, int K)
{
    __shared__ __align__(16) float As[2][8][132];
    __shared__ __align__(16) float Bs[2][8][132];
    A    += (size_t)blockIdx.z * aBatch;
    Bm   += (size_t)blockIdx.z * bBatch;
    if (bias) bias += (size_t)blockIdx.z * biasBatch;
    C    += (size_t)blockIdx.z * cBatch;

    const int n0 = blockIdx.x * 128;
    const int m0 = blockIdx.y * 128;
    const int tid = threadIdx.x;
    const int tx = tid & 15;
    const int ty = tid >> 4;

    const int amr = tid >> 1;
    const int akb = (tid & 1) << 2;
    const float* aPtr = A + (size_t)(m0 + amr) * lda + akb;
    const int bnr = tid >> 1;
    const int bkb = (tid & 1) << 2;
    const int bkr = tid >> 5;
    const int bnc = (tid & 31) << 2;
    const float* bPtr = BT ? (Bm + (size_t)(n0 + bnr) * ldb + bkb)
                           : (Bm + (size_t)bkr * ldb + n0 + bnc);
    const bool bok = EXACT || (BT ? (n0 + bnr) < N : (n0 + bnc + 4) <= N);

    float acc[8][8] = {};
    float aR[4], bR[4];
    const float4 z4 = make_float4(0.f, 0.f, 0.f, 0.f);
    const int nch = (K + 7) >> 3;

    if (EXACT) {
        float4 v = *(const float4*)aPtr;
        aR[0] = v.x; aR[1] = v.y; aR[2] = v.z; aR[3] = v.w;
    } else {
        #pragma unroll
        for (int j = 0; j < 4; j++) aR[j] = (akb + j < K) ? aPtr[j] : 0.f;
    }
    aPtr += 8;
    if (BT) {
        float4 v = (bok && (EXACT || bkb + 4 <= K)) ? *(const float4*)bPtr : z4;
        bR[0] = v.x; bR[1] = v.y; bR[2] = v.z; bR[3] = v.w;
        bPtr += 8;
    } else {
        float4 v = (bok && (EXACT || bkr < K)) ? *(const float4*)bPtr : z4;
        bR[0] = v.x; bR[1] = v.y; bR[2] = v.z; bR[3] = v.w;
        bPtr += (size_t)8 * ldb;
    }
    #pragma unroll
    for (int j = 0; j < 4; j++) As[0][akb + j][amr] = aR[j];
    if (BT) {
        #pragma unroll
        for (int j = 0; j < 4; j++) Bs[0][bkb + j][bnr] = bR[j];
    } else {
        *(float4*)&Bs[0][bkr][bnc] = make_float4(bR[0], bR[1], bR[2], bR[3]);
    }
    __syncthreads();

    for (int kc = 0; kc < nch; kc++) {
        const int cur = kc & 1, nxt = cur ^ 1;
        const bool more = (kc + 1) < nch;
        if (more) {
            const int k0 = (kc + 1) << 3;
            if (EXACT) {
                float4 v = *(const float4*)aPtr;
                aR[0] = v.x; aR[1] = v.y; aR[2] = v.z; aR[3] = v.w;
            } else {
                #pragma unroll
                for (int j = 0; j < 4; j++) aR[j] = (k0 + akb + j < K) ? aPtr[j] : 0.f;
            }
            aPtr += 8;
            if (BT) {
                float4 v = (bok && (EXACT || k0 + bkb + 4 <= K)) ? *(const float4*)bPtr : z4;
                bR[0] = v.x; bR[1] = v.y; bR[2] = v.z; bR[3] = v.w;
                bPtr += 8;
            } else {
                float4 v = (bok && (EXACT || k0 + bkr < K)) ? *(const float4*)bPtr : z4;
                bR[0] = v.x; bR[1] = v.y; bR[2] = v.z; bR[3] = v.w;
                bPtr += (size_t)8 * ldb;
            }
        }
        #pragma unroll
        for (int k = 0; k < 8; k++) {
            float4 a0 = *(const float4*)&As[cur][k][ty << 3];
            float4 a1 = *(const float4*)&As[cur][k][(ty << 3) + 4];
            float4 b0 = *(const float4*)&Bs[cur][k][tx << 2];
            float4 b1 = *(const float4*)&Bs[cur][k][64 + (tx << 2)];
            float av[8] = {a0.x, a0.y, a0.z, a0.w, a1.x, a1.y, a1.z, a1.w};
            float bv[8] = {b0.x, b0.y, b0.z, b0.w, b1.x, b1.y, b1.z, b1.w};
            #pragma unroll
            for (int i = 0; i < 8; i++) {
                #pragma unroll
                for (int j = 0; j < 8; j++) acc[i][j] += av[i] * bv[j];
            }
        }
        if (more) {
            #pragma unroll
            for (int j = 0; j < 4; j++) As[nxt][akb + j][amr] = aR[j];
            if (BT) {
                #pragma unroll
                for (int j = 0; j < 4; j++) Bs[nxt][bkb + j][bnr] = bR[j];
            } else {
                *(float4*)&Bs[nxt][bkr][bnc] = make_float4(bR[0], bR[1], bR[2], bR[3]);
            }
            __syncthreads();
        }
    }

    #pragma unroll
    for (int gEp = 0; gEp < 2; gEp++) {
        const int c = n0 + gEp * 64 + (tx << 2);
        const int jb = gEp * 4;
        if (EXACT || c + 4 <= N) {
            float bv0 = bias ? bias[c]     : 0.f;
            float bv1 = bias ? bias[c + 1] : 0.f;
            float bv2 = bias ? bias[c + 2] : 0.f;
            float bv3 = bias ? bias[c + 3] : 0.f;
            #pragma unroll
            for (int i = 0; i < 8; i++) {
                int m = m0 + (ty << 3) + i;
                float v0 = acc[i][jb]     + bv0;
                float v1 = acc[i][jb + 1] + bv1;
                float v2 = acc[i][jb + 2] + bv2;
                float v3 = acc[i][jb + 3] + bv3;
                if (EPI == 1) { v0 = leakyf(v0); v1 = leakyf(v1); v2 = leakyf(v2); v3 = leakyf(v3); }
                if (EPI == 2) { v0 = fmaxf(v0, 0.f); v1 = fmaxf(v1, 0.f); v2 = fmaxf(v2, 0.f); v3 = fmaxf(v3, 0.f); }
                *(float4*)&C[(size_t)m * ldc + c] = make_float4(v0, v1, v2, v3);
            }
        }
    }
}

// =================== specialized f1 kernel ==================
__global__ void __launch_bounds__(256, 2) f1_kernel(
    const float* __restrict__ feat, const float* __restrict__ W1,
    const float* __restrict__ b1, float* __restrict__ out)
{
    __shared__ __align__(16) float As[2][8][260];
    __shared__ __align__(16) float Bs[2][8][36];
    const int m0 = blockIdx.x * 256;
    const int tid = threadIdx.x;
    const int tx = tid & 7;
    const int ty = tid >> 3;
    const float* aPtr = feat + (size_t)(m0 + tid) * NEF;
    const bool bload = tid < 64;
    const int bk = tid >> 3;
    const int bc = (tid & 7) << 2;

    float acc[8][4] = {};
    float4 aA, aB, bv;
    const int nch = NEF / 8;

    aA = *(const float4*)aPtr; aB = *(const float4*)(aPtr + 4); aPtr += 8;
    if (bload) bv = *(const float4*)&W1[(size_t)bk * NAU + bc];
    As[0][0][tid] = aA.x; As[0][1][tid] = aA.y; As[0][2][tid] = aA.z; As[0][3][tid] = aA.w;
    As[0][4][tid] = aB.x; As[0][5][tid] = aB.y; As[0][6][tid] = aB.z; As[0][7][tid] = aB.w;
    if (bload) *(float4*)&Bs[0][bk][bc] = bv;
    __syncthreads();

    for (int kc = 0; kc < nch; kc++) {
        const int cur = kc & 1, nxt = cur ^ 1;
        const bool more = (kc + 1) < nch;
        if (more) {
            aA = *(const float4*)aPtr; aB = *(const float4*)(aPtr + 4); aPtr += 8;
            if (bload) bv = *(const float4*)&W1[(size_t)((kc + 1) * 8 + bk) * NAU + bc];
        }
        #pragma unroll
        for (int k = 0; k < 8; k++) {
            float4 a0 = *(const float4*)&As[cur][k][ty << 3];
            float4 a1 = *(const float4*)&As[cur][k][(ty << 3) + 4];
            float4 b4 = *(const float4*)&Bs[cur][k][tx << 2];
            float av[8] = {a0.x, a0.y, a0.z, a0.w, a1.x, a1.y, a1.z, a1.w};
            #pragma unroll
            for (int i = 0; i < 8; i++) {
                acc[i][0] += av[i] * b4.x; acc[i][1] += av[i] * b4.y;
                acc[i][2] += av[i] * b4.z; acc[i][3] += av[i] * b4.w;
            }
        }
        if (more) {
            As[nxt][0][tid] = aA.x; As[nxt][1][tid] = aA.y; As[nxt][2][tid] = aA.z; As[nxt][3][tid] = aA.w;
            As[nxt][4][tid] = aB.x; As[nxt][5][tid] = aB.y; As[nxt][6][tid] = aB.z; As[nxt][7][tid] = aB.w;
            if (bload) *(float4*)&Bs[nxt][bk][bc] = bv;
            __syncthreads();
        }
    }

    const int c = tx << 2;
    float bb0 = b1[c], bb1 = b1[c + 1], bb2 = b1[c + 2], bb3 = b1[c + 3];
    #pragma unroll
    for (int i = 0; i < 8; i++) {
        int m = m0 + (ty << 3) + i;
        float v0 = fmaxf(acc[i][0] + bb0, 0.f);
        float v1 = fmaxf(acc[i][1] + bb1, 0.f);
        float v2 = fmaxf(acc[i][2] + bb2, 0.f);
        float v3 = fmaxf(acc[i][3] + bb3, 0.f);
        *(float4*)&out[(size_t)m * NAU + c] = make_float4(v0, v1, v2, v3);
    }
}

// ---------------- LayerNorm over rows of length 512 (in-place) ----------------
__global__ void __launch_bounds__(128) ln_rows_kernel(float* __restrict__ X,
    const float* __restrict__ gg, const float* __restrict__ bb)
{
    __shared__ float red[32];
    size_t row = blockIdx.x;
    float* xr = X + row * NEF;
    int tid = threadIdx.x;
    float v[4];
    #pragma unroll
    for (int j = 0; j < 4; j++) v[j] = xr[tid + 128 * j];
    float s = v[0] + v[1] + v[2] + v[3];
    float mean = blockSum(s, red) * (1.f / NEF);
    float sq = 0.f;
    #pragma unroll
    for (int j = 0; j < 4; j++) { float d = v[j] - mean; sq += d * d; }
    float var = blockSum(sq, red) * (1.f / NEF);
    float r = rsqrtf(var + 1e-5f);
    #pragma unroll
    for (int j = 0; j < 4; j++) {
        int cidx = tid + 128 * j;
        xr[cidx] = (v[j] - mean) * r * gg[cidx] + bb[cidx];
    }
}

// ---------------- pack + init + gather ----------------
__global__ void pack_kernel(const float* __restrict__ W_ih, const float* __restrict__ W_hh,
                            const float* __restrict__ b_ih, const float* __restrict__ b_hh)
{
    size_t idx = (size_t)blockIdx.x * blockDim.x + threadIdx.x;
    if (idx < (size_t)N4U * NKS) {
        int j = (int)(idx / NKS), k = (int)(idx % NKS);
        g_Wcat[idx] = (k < NEF) ? W_ih[(size_t)j * (NEF + NET) + k]
                                : W_hh[(size_t)j * NU + (k - NEF)];
    }
    if (idx < N4U) g_bsum[idx] = b_ih[idx] + b_hh[idx];
}

__global__ void init_kernel(const float* __restrict__ c0)
{
    int idx = blockIdx.x * blockDim.x + threadIdx.x;
    if (idx == 0) g_barCnt = 0u;
    if (idx < NB * NU) g_c[idx] = c0[idx];
}

__global__ void gather_emb_kernel(const float* __restrict__ emb, const int* __restrict__ text)
{
    size_t idx = (size_t)blockIdx.x * blockDim.x + threadIdx.x;
    if (idx >= (size_t)NT * NB * NET) return;
    int r = (int)(idx >> 9);
    int col = (int)(idx & 511);
    int t = r / NB, b = r % NB;
    int tok = text[b * NT + t];
    g_embseq[idx] = emb[(size_t)tok * NET + col];
}

// =================== persistent recurrence kernel =====================================
// grid NRB=256 x 256 threads, 2 CTAs/SM (co-resident). Per step t:
//   A (blocks 0..127, b=bid): LSTM(t-1) from gpart+embg (or a0 at t=0) -> a_s;
//     h2, scores, softmax -> g_wbuf; xfull a-part; aseq[t].     [barrier]
//   B (all blocks, b=bid>>1, half=bid&1): ctx 256 cols/block -> xfull. [barrier]
//   C (all blocks, ntile=bid&15, ks=bid>>4): gates tile 128x128xK64 -> gpart. [barrier]
// Final (t=NT): LSTM only -> aseq[NT].
// Cross-block reads (gpart, wbuf, xfull) use __ldcg: L1 is not coherent across SMs.
__global__ void __launch_bounds__(256, 2) rec_kernel(
    const float* __restrict__ a0v,
    const float* __restrict__ W2, const float* __restrict__ b2,
    const float* __restrict__ V, const float* __restrict__ bV,
    const float* __restrict__ lng, const float* __restrict__ lnb,
    float* __restrict__ attn_out)
{
    __shared__ __align__(16) float As[2][8][132];
    __shared__ __align__(16) float Bs[2][8][132];
    __shared__ float a_s[NU];
    __shared__ float ss[NG];
    __shared__ float h2s[NAU];
    __shared__ float part[8][NAU];
    __shared__ float red[32];

    const int tid = threadIdx.x;
    const int bid = blockIdx.x;
    unsigned int epoch = 0;

    for (int t = 0; t <= NT; t++) {
        // ---------------- Phase A ----------------
        if (bid < NB) {
            const int b = bid;
            if (t == 0) {
                a_s[tid]       = a0v[b * NU + tid];
                a_s[tid + 256] = a0v[b * NU + tid + 256];
            } else {
                const int u1 = tid, u2 = tid + 256;
                const float* er = g_embg + (size_t)(t - 1) * NB * N4U + (size_t)b * N4U;
                float gi1 = er[u1], gf1 = er[NU + u1], gg1 = er[2 * NU + u1], go1 = er[3 * NU + u1];
                float gi2 = er[u2], gf2 = er[NU + u2], gg2 = er[2 * NU + u2], go2 = er[3 * NU + u2];
                #pragma unroll 4
                for (int z = 0; z < NSK; z++) {
                    const float* gr = g_gpart + (size_t)z * NB * N4U + (size_t)b * N4U;
                    gi1 += __ldcg(gr + u1); gf1 += __ldcg(gr + NU + u1);
                    gg1 += __ldcg(gr + 2 * NU + u1); go1 += __ldcg(gr + 3 * NU + u1);
                    gi2 += __ldcg(gr + u2); gf2 += __ldcg(gr + NU + u2);
                    gg2 += __ldcg(gr + 2 * NU + u2); go2 += __ldcg(gr + 3 * NU + u2);
                }
                float c1 = sigmoidf(gf1) * g_c[b * NU + u1] + sigmoidf(gi1) * tanhf(gg1);
                float c2 = sigmoidf(gf2) * g_c[b * NU + u2] + sigmoidf(gi2) * tanhf(gg2);
                float h1 = sigmoidf(go1) * tanhf(c1);
                float h2v = sigmoidf(go2) * tanhf(c2);
                g_c[b * NU + u1] = c1; g_c[b * NU + u2] = c2;
                float hl1 = leakyf(h1), hl2 = leakyf(h2v);
                float mean = blockSum(hl1 + hl2, red) * (1.f / NU);
                float d1 = hl1 - mean, d2 = hl2 - mean;
                float var = blockSum(d1 * d1 + d2 * d2, red) * (1.f / NU);
                float rr = rsqrtf(var + 1e-5f);
                float av1 = d1 * rr * lng[u1] + lnb[u1];
                float av2 = d2 * rr * lng[u2] + lnb[u2];
                a_s[u1] = av1; a_s[u2] = av2;
                float* aseq_t = g_aseq + (size_t)t * NB * NU + (size_t)b * NU;
                aseq_t[u1] = av1; aseq_t[u2] = av2;
            }
            if (t < NT) {
                g_xfull[(size_t)b * NKS + NEF + tid]       = a_s[tid];
                g_xfull[(size_t)b * NKS + NEF + tid + 256] = a_s[tid + 256];
                __syncthreads();
                // h2 = relu(a @ W2 + b2): 8 segments x 64 k
                {
                    int au = tid & 31, seg = tid >> 5;
                    float acc = 0.f;
                    #pragma unroll 8
                    for (int kk = 0; kk < 64; kk++) {
                        int k = seg * 64 + kk;
                        acc += a_s[k] * W2[k * NAU + au];
                    }
                    part[seg][au] = acc;
                }
                __syncthreads();
                if (tid < NAU) {
                    float s = 0.f;
                    #pragma unroll
                    for (int i = 0; i < 8; i++) s += part[i][tid];
                    h2s[tid] = fmaxf(s + b2[tid], 0.f);
                }
                __syncthreads();
                // scores: 8 warps, 2 groups per iteration (ILP)
                {
                    int wid = tid >> 5, lane = tid & 31;
                    float h2l = h2s[lane], Vl = V[lane];
                    for (int g = wid; g < NG; g += 16) {
                        int g2 = g + 8;
                        float v1 = tanhf(g_f1[((size_t)b * NG + g) * NAU + lane] + h2l) * Vl;
                        float v2 = (g2 < NG) ? tanhf(g_f1[((size_t)b * NG + g2) * NAU + lane] + h2l) * Vl : 0.f;
                        #pragma unroll
                        for (int o = 16; o; o >>= 1) {
                            v1 += __shfl_xor_sync(0xffffffffu, v1, o);
                            v2 += __shfl_xor_sync(0xffffffffu, v2, o);
                        }
                        if (lane == 0) {
                            ss[g] = v1 + bV[0];
                            if (g2 < NG) ss[g2] = v2 + bV[0];
                        }
                    }
                }
                __syncthreads();
                // softmax over 360
                float mx = -INFINITY;
                for (int g = tid; g < NG; g += 256) mx = fmaxf(mx, ss[g]);
                mx = blockMax(mx, red);
                float sum = 0.f;
                for (int g = tid; g < NG; g += 256) { float e = expf(ss[g] - mx); ss[g] = e; sum += e; }
                sum = blockSum(sum, red);
                float inv = 1.f / sum;
                for (int g = tid; g < NG; g += 256) {
                    float w = ss[g] * inv;
                    g_wbuf[b * NG + g] = w;
                    if (attn_out) attn_out[((size_t)b * NT + t) * NG + g] = w;
                }
            }
        }
        if (t == NT) break;
        grid_sync(epoch);                       // wbuf + xfull a-part ready

        // ---------------- Phase B: ctx ----------------
        {
            const int bb = bid >> 1, half = bid & 1;
            for (int g = tid; g < NG; g += 256) ss[g] = __ldcg(&g_wbuf[bb * NG + g]);
            __syncthreads();
            const int ef = half * 256 + tid;
            const float* fb = g_feat + (size_t)bb * NG * NEF + ef;
            float acc = 0.f;
            #pragma unroll 8
            for (int g = 0; g < NG; g++) acc += ss[g] * fb[(size_t)g * NEF];
            g_xfull[(size_t)bb * NKS + ef] = acc;
        }
        grid_sync(epoch);                       // xfull ready

        // ---------------- Phase C: gates tile (inlined gemm128 BT inner) ----------------
        {
            const int ntile = bid & 15;
            const int ks = bid >> 4;
            const float* Ax = g_xfull + ks * NKSP;                          // lda = NKS
            const float* Bw = g_Wcat + (size_t)(ntile * 128) * NKS + ks * NKSP;
            float* Cp = g_gpart + (size_t)ks * NB * N4U;                    // ldc = N4U

            const int tx = tid & 15;
            const int ty = tid >> 4;
            const int amr = tid >> 1;
            const int akb = (tid & 1) << 2;
            const float* aPtr = Ax + (size_t)amr * NKS + akb;
            const float* bPtr = Bw + (size_t)amr * NKS + akb;               // bnr==amr, bkb==akb

            float acc[8][8] = {};
            float4 av4, bv4;
            av4 = __ldcg((const float4*)aPtr); aPtr += 8;
            bv4 = *(const float4*)bPtr;        bPtr += 8;
            As[0][akb + 0][amr] = av4.x; As[0][akb + 1][amr] = av4.y;
            As[0][akb + 2][amr] = av4.z; As[0][akb + 3][amr] = av4.w;
            Bs[0][akb + 0][amr] = bv4.x; Bs[0][akb + 1][amr] = bv4.y;
            Bs[0][akb + 2][amr] = bv4.z; Bs[0][akb + 3][amr] = bv4.w;
            __syncthreads();

            #pragma unroll 1
            for (int kc = 0; kc < 8; kc++) {
                const int cur = kc & 1, nxt = cur ^ 1;
                const bool more = kc < 7;
                if (more) {
                    av4 = __ldcg((const float4*)aPtr); aPtr += 8;
                    bv4 = *(const float4*)bPtr;        bPtr += 8;
                }
                #pragma unroll
                for (int k = 0; k < 8; k++) {
                    float4 a0 = *(const float4*)&As[cur][k][ty << 3];
                    float4 a1 = *(const float4*)&As[cur][k][(ty << 3) + 4];
                    float4 b0 = *(const float4*)&Bs[cur][k][tx << 2];
                    float4 b1 = *(const float4*)&Bs[cur][k][64 + (tx << 2)];
                    float av[8] = {a0.x, a0.y, a0.z, a0.w, a1.x, a1.y, a1.z, a1.w};
                    float bv[8] = {b0.x, b0.y, b0.z, b0.w, b1.x, b1.y, b1.z, b1.w};
                    #pragma unroll
                    for (int i = 0; i < 8; i++) {
                        #pragma unroll
                        for (int j = 0; j < 8; j++) acc[i][j] += av[i] * bv[j];
                    }
                }
                if (more) {
                    As[nxt][akb + 0][amr] = av4.x; As[nxt][akb + 1][amr] = av4.y;
                    As[nxt][akb + 2][amr] = av4.z; As[nxt][akb + 3][amr] = av4.w;
                    Bs[nxt][akb + 0][amr] = bv4.x; Bs[nxt][akb + 1][amr] = bv4.y;
                    Bs[nxt][akb + 2][amr] = bv4.z; Bs[nxt][akb + 3][amr] = bv4.w;
                    __syncthreads();
                }
            }
            #pragma unroll
            for (int gEp = 0; gEp < 2; gEp++) {
                const int c = ntile * 128 + gEp * 64 + (tx << 2);
                const int jb = gEp * 4;
                #pragma unroll
                for (int i = 0; i < 8; i++) {
                    int m = (ty << 3) + i;
                    *(float4*)&Cp[(size_t)m * N4U + c] =
                        make_float4(acc[i][jb], acc[i][jb + 1], acc[i][jb + 2], acc[i][jb + 3]);
                }
            }
        }
        grid_sync(epoch);                       // gpart ready
    }
}

// ---------------- batched vocab softmax: r = r0 + blockIdx.x ----------
__global__ void __launch_bounds__(512) vsm_kernel(
    const float* __restrict__ logits, float* __restrict__ out, int r0)
{
    __shared__ float red[32];
    int r = r0 + blockIdx.x, tid = threadIdx.x;
    int t = r / NB, b = r % NB;
    const float* lr = logits + (size_t)r * NVOC;
    float* orow = out + ((size_t)b * NT + t) * NVOC;
    float mx = -INFINITY;
    for (int v = tid; v < NVOC; v += 512) mx = fmaxf(mx, lr[v]);
    mx = blockMax(mx, red);
    float s = 0.f;
    for (int v = tid; v < NVOC; v += 512) { float e = expf(lr[v] - mx); orow[v] = e; s += e; }
    s = blockSum(s, red);
    float inv = 1.f / s;
    for (int v = tid; v < NVOC; v += 512) orow[v] *= inv;
}

// ---------------- host ----------------
extern "C" void kernel_launch(void* const* d_in, const int* in_sizes, int n_in,
                              void* d_out, int out_size)
{
    const float* features = (const float*)d_in[0];
    const int*   text     = (const int*)  d_in[1];
    const float* a0       = (const float*)d_in[2];
    const float* c0       = (const float*)d_in[3];
    const float* enc_W    = (const float*)d_in[4];
    const float* enc_b    = (const float*)d_in[5];
    const float* enc_ln_g = (const float*)d_in[6];
    const float* enc_ln_b = (const float*)d_in[7];
    const float* attn_W1  = (const float*)d_in[8];
    const float* attn_b1  = (const float*)d_in[9];
    const float* attn_W2  = (const float*)d_in[10];
    const float* attn_b2  = (const float*)d_in[11];
    const float* attn_V   = (const float*)d_in[12];
    const float* attn_bV  = (const float*)d_in[13];
    const float* emb      = (const float*)d_in[14];
    const float* W_ih     = (const float*)d_in[15];
    const float* W_hh     = (const float*)d_in[16];
    const float* b_ih     = (const float*)d_in[17];
    const float* b_hh     = (const float*)d_in[18];
    const float* ln_g     = (const float*)d_in[19];
    const float* ln_b     = (const float*)d_in[20];
    const float* dec_W1   = (const float*)d_in[21];
    const float* dec_b1   = (const float*)d_in[22];
    const float* dec_W2   = (const float*)d_in[23];
    const float* dec_b2   = (const float*)d_in[24];

    float *p_feat, *p_f1, *p_aseq, *p_es, *p_eg, *p_bs, *p_d1, *p_lg;
    cudaGetSymbolAddress((void**)&p_feat, g_feat);
    cudaGetSymbolAddress((void**)&p_f1,   g_f1);
    cudaGetSymbolAddress((void**)&p_aseq, g_aseq);
    cudaGetSymbolAddress((void**)&p_es,   g_embseq);
    cudaGetSymbolAddress((void**)&p_eg,   g_embg);
    cudaGetSymbolAddress((void**)&p_bs,   g_bsum);
    cudaGetSymbolAddress((void**)&p_d1,   g_d1big);
    cudaGetSymbolAddress((void**)&p_lg,   g_lgbig);

    float* out = (float*)d_out;
    float* attn_out = nullptr;
    long long need = (long long)NB * NT * NVOC + (long long)NB * NT * NG;
    if ((long long)out_size >= need) attn_out = out + (size_t)NB * NT * NVOC;

    // ---- one-time stream/event setup (first call is NOT under capture) ----
    static cudaStream_t s2 = nullptr;
    static cudaEvent_t evFork = nullptr, evPre = nullptr;
    if (s2 == nullptr) {
        cudaStreamCreateWithFlags(&s2, cudaStreamNonBlocking);
        cudaEventCreateWithFlags(&evFork, cudaEventDisableTiming);
        cudaEventCreateWithFlags(&evPre,  cudaEventDisableTiming);
    }
    cudaStream_t s0 = 0;

    // ---- fork stream2: prologue (pack -> gather -> embg) ----
    cudaEventRecord(evFork, s0);
    cudaStreamWaitEvent(s2, evFork, 0);
    pack_kernel<<<(int)(((size_t)N4U * NKS + 255) / 256), 256, 0, s2>>>(W_ih, W_hh, b_ih, b_hh);
    gather_emb_kernel<<<(int)(((size_t)NT * NB * NET + 255) / 256), 256, 0, s2>>>(emb, text);
    {
        dim3 geg(N4U / 128, (NT * NB) / 128, 1);
        gemm128_kernel<true, 0, true><<<geg, 256, 0, s2>>>(
            p_es, NET, 0,
            W_ih + NEF, NEF + NET, 0,
            p_bs, 0,
            p_eg, N4U, 0,
            NT * NB, N4U, NET);
    }
    cudaEventRecord(evPre, s2);

    // ---- main stream: init + encoder path ----
    init_kernel<<<(NB * NU + 255) / 256, 256, 0, s0>>>(c0);
    {
        dim3 ge(NEF / 128, NB / 128, NG);
        gemm128_kernel<false, 1, false><<<ge, 256, 0, s0>>>(
            features, NG * NGI, (size_t)NGI,
            enc_W, NEF, (size_t)NGI * NEF,
            enc_b, (size_t)NEF,
            p_feat, NG * NEF, (size_t)NEF,
            NB, NEF, NGI);
        ln_rows_kernel<<<NB * NG, 128, 0, s0>>>(p_feat, enc_ln_g, enc_ln_b);
    }
    f1_kernel<<<(NB * NG) / 256, 256, 0, s0>>>(p_feat, attn_W1, attn_b1, p_f1);

    // ---- join prologue, then the persistent recurrence kernel (runs ALONE) ----
    cudaStreamWaitEvent(s0, evPre, 0);
    rec_kernel<<<NRB, 256, 0, s0>>>(a0, attn_W2, attn_b2, attn_V, attn_bV,
                                    ln_g, ln_b, attn_out);

    // ---- deferred decoder over all T*B rows (row r = t*NB + b) ----
    {
        dim3 gd1(256 / 128, (NT * NB) / 128, 1);
        gemm128_kernel<false, 1, true><<<gd1, 256, 0, s0>>>(
            p_aseq + (size_t)NB * NU, NU, 0, dec_W1, 256, 0, dec_b1, 0,
            p_d1, 256, 0, NT * NB, 256, NU);
    }
    {
        dim3 gd2((NVOC + 127) / 128, (NT * NB) / 128, 1);
        gemm128_kernel<false, 0, false><<<gd2, 256, 0, s0>>>(
            p_d1, 256, 0, dec_W2, NVOC, 0, dec_b2, 0,
            p_lg, NVOC, 0, NT * NB, NVOC, 256);
    }
    vsm_kernel<<<NT * NB, 512, 0, s0>>>(p_lg, out, 0);
}